// round 1
// baseline (speedup 1.0000x reference)
#include <cuda_runtime.h>

#define NN 50000
#define EE 800000
#define RR 8
#define HD 128
#define KDIM (RR * HD)   // 1024

// ---------------- scratch (device globals; no allocation allowed) ----------
__device__ float g_y[(size_t)NN * KDIM];   // 204.8 MB accumulation buffer
__device__ float g_ex[EE];                 // exp(alpha) per edge
__device__ float g_denom[NN];              // softmax denominators
__device__ float g_wq[RR * HD];            // W_r @ q
__device__ float g_wk[RR * HD];            // W_r @ k

// ---------------- zero y + denom -------------------------------------------
__global__ void zero_kernel() {
    size_t i = (size_t)blockIdx.x * blockDim.x + threadIdx.x;
    size_t stride = (size_t)gridDim.x * blockDim.x;
    float4* y4 = (float4*)g_y;
    const size_t ny4 = (size_t)NN * KDIM / 4;
    float4 z = make_float4(0.f, 0.f, 0.f, 0.f);
    for (size_t j = i; j < ny4; j += stride) y4[j] = z;
    float4* d4 = (float4*)g_denom;
    for (size_t j = i; j < NN / 4; j += stride) d4[j] = z;
}

// ---------------- Wq[r] = W_r @ q, Wk[r] = W_r @ k --------------------------
__global__ void wqwk_kernel(const float* __restrict__ W,
                            const float* __restrict__ q,
                            const float* __restrict__ k) {
    int w = (blockIdx.x * blockDim.x + threadIdx.x) >> 5;  // 0..1023 = r*128+d
    int lane = threadIdx.x & 31;
    if (w >= RR * HD) return;
    const float* row = W + (size_t)w * HD;
    float sq = 0.f, sk = 0.f;
#pragma unroll
    for (int j = lane; j < HD; j += 32) {
        float wv = row[j];
        sq += wv * q[j];
        sk += wv * k[j];
    }
#pragma unroll
    for (int o = 16; o; o >>= 1) {
        sq += __shfl_xor_sync(0xffffffffu, sq, o);
        sk += __shfl_xor_sync(0xffffffffu, sk, o);
    }
    if (lane == 0) {
        g_wq[w] = sq;
        g_wk[w] = sk;
    }
}

// ---------------- per-edge logits: ex = exp(leaky_relu(qi+kj)) --------------
// One warp per edge. x rows are L2-resident (25.6 MB).
__global__ void score_kernel(const float* __restrict__ x,
                             const int* __restrict__ ei,
                             const int* __restrict__ et) {
    int e = (blockIdx.x * blockDim.x + threadIdx.x) >> 5;
    if (e >= EE) return;
    int lane = threadIdx.x & 31;
    int src = ei[e];
    int dst = ei[EE + e];
    int r = et[e];
    const float4* x4 = (const float4*)x;
    float4 xs = x4[src * 32 + lane];
    float4 xd = x4[dst * 32 + lane];
    float4 wk4 = ((const float4*)g_wk)[r * 32 + lane];
    float4 wq4 = ((const float4*)g_wq)[r * 32 + lane];
    float p = xs.x * wk4.x + xs.y * wk4.y + xs.z * wk4.z + xs.w * wk4.w
            + xd.x * wq4.x + xd.y * wq4.y + xd.z * wq4.z + xd.w * wq4.w;
#pragma unroll
    for (int o = 16; o; o >>= 1) p += __shfl_xor_sync(0xffffffffu, p, o);
    if (lane == 0) {
        float a = p > 0.f ? p : 0.2f * p;   // leaky_relu, slope 0.2
        float v = __expf(a);                // alpha ~ O(1): no max-shift needed
        g_ex[e] = v;
        atomicAdd(&g_denom[dst], v);
    }
}

// ---------------- scatter: y[dst, r*128 + :] += a * x[src, :] ---------------
__global__ void scatter_kernel(const float* __restrict__ x,
                               const int* __restrict__ ei,
                               const int* __restrict__ et) {
    int e = (blockIdx.x * blockDim.x + threadIdx.x) >> 5;
    if (e >= EE) return;
    int lane = threadIdx.x & 31;
    int src = ei[e];
    int dst = ei[EE + e];
    int r = et[e];
    float a = g_ex[e] / (g_denom[dst] + 1e-16f);
    float4 v = ((const float4*)x)[src * 32 + lane];
    v.x *= a; v.y *= a; v.z *= a; v.w *= a;
    float* p = &g_y[(size_t)dst * KDIM + r * HD + lane * 4];
    asm volatile("red.global.add.v4.f32 [%0], {%1,%2,%3,%4};"
                 :: "l"(p), "f"(v.x), "f"(v.y), "f"(v.z), "f"(v.w)
                 : "memory");
}

// ---------------- out = relu( y[M,1024] @ W[1024,128] + b ) -----------------
#define BM 128
#define BN 128
#define BK 16
#define TM 8
#define TN 8

__global__ __launch_bounds__(256, 2)
void gemm_bias_relu(const float* __restrict__ B,   // W flattened [1024,128]
                    const float* __restrict__ bias,
                    float* __restrict__ C, int M) {
    __shared__ float As[BK][BM];
    __shared__ float Bs[BK][BN];
    int tid = threadIdx.x;
    int block_m = blockIdx.x * BM;
    int tx = tid & 15;         // 0..15 -> 8 cols each
    int ty = tid >> 4;         // 0..15 -> 8 rows each

    float acc[TM][TN];
#pragma unroll
    for (int i = 0; i < TM; i++)
#pragma unroll
        for (int j = 0; j < TN; j++) acc[i][j] = 0.f;

    int arow = tid >> 2;           // 0..63
    int acol = (tid & 3) << 2;     // 0,4,8,12
    int brow = tid >> 5;           // 0..7
    int bcol = (tid & 31) << 2;    // 0..124

    for (int k0 = 0; k0 < KDIM; k0 += BK) {
#pragma unroll
        for (int i = 0; i < 2; i++) {
            int m = arow + i * 64;
            int gm = block_m + m;
            float4 v = make_float4(0.f, 0.f, 0.f, 0.f);
            if (gm < M) v = *(const float4*)&g_y[(size_t)gm * KDIM + k0 + acol];
            As[acol + 0][m] = v.x;
            As[acol + 1][m] = v.y;
            As[acol + 2][m] = v.z;
            As[acol + 3][m] = v.w;
        }
#pragma unroll
        for (int i = 0; i < 2; i++) {
            int kk = brow + i * 8;
            *(float4*)&Bs[kk][bcol] = *(const float4*)&B[(size_t)(k0 + kk) * BN + bcol];
        }
        __syncthreads();
#pragma unroll
        for (int k = 0; k < BK; k++) {
            float am[TM], bn[TN];
#pragma unroll
            for (int i = 0; i < TM; i++) am[i] = As[k][ty * TM + i];
#pragma unroll
            for (int j = 0; j < TN; j++) bn[j] = Bs[k][tx * TN + j];
#pragma unroll
            for (int i = 0; i < TM; i++)
#pragma unroll
                for (int j = 0; j < TN; j++) acc[i][j] += am[i] * bn[j];
        }
        __syncthreads();
    }

#pragma unroll
    for (int i = 0; i < TM; i++) {
        int gm = block_m + ty * TM + i;
        if (gm >= M) continue;
#pragma unroll
        for (int j = 0; j < TN; j += 4) {
            int n = tx * TN + j;
            float4 v;
            v.x = fmaxf(acc[i][j + 0] + bias[n + 0], 0.f);
            v.y = fmaxf(acc[i][j + 1] + bias[n + 1], 0.f);
            v.z = fmaxf(acc[i][j + 2] + bias[n + 2], 0.f);
            v.w = fmaxf(acc[i][j + 3] + bias[n + 3], 0.f);
            *(float4*)&C[(size_t)gm * HD + n] = v;
        }
    }
}

// ---------------- driver ----------------------------------------------------
static void run_one_graph(const float* x, const int* ei, const int* et,
                          const float* W, const float* q, const float* k,
                          const float* b, float* out) {
    zero_kernel<<<2048, 256>>>();
    wqwk_kernel<<<(RR * HD) / 8, 256>>>(W, q, k);
    score_kernel<<<EE / 8, 256>>>(x, ei, et);
    scatter_kernel<<<EE / 8, 256>>>(x, ei, et);
    gemm_bias_relu<<<(NN + BM - 1) / BM, 256>>>(W, b, out, NN);
}

extern "C" void kernel_launch(void* const* d_in, const int* in_sizes, int n_in,
                              void* d_out, int out_size) {
    const float* x1  = (const float*)d_in[0];
    const int*   ei1 = (const int*)d_in[1];
    const int*   et1 = (const int*)d_in[2];
    const float* x2  = (const float*)d_in[3];
    const int*   ei2 = (const int*)d_in[4];
    const int*   et2 = (const int*)d_in[5];
    const float* W1  = (const float*)d_in[6];
    const float* q1  = (const float*)d_in[7];
    const float* k1  = (const float*)d_in[8];
    const float* b1  = (const float*)d_in[9];
    const float* W2  = (const float*)d_in[10];
    const float* q2  = (const float*)d_in[11];
    const float* k2  = (const float*)d_in[12];
    const float* b2  = (const float*)d_in[13];

    float* out = (float*)d_out;
    run_one_graph(x1, ei1, et1, W1, q1, k1, b1, out);
    run_one_graph(x2, ei2, et2, W2, q2, k2, b2, out + (size_t)NN * HD);
}

// round 2
// speedup vs baseline: 1.8764x; 1.8764x over previous
#include <cuda_runtime.h>
#include <cstdint>

#define NN 50000
#define EE 800000
#define RR 8
#define HD 128

#define GM 128
#define PA 132          // x-tile smem row stride (floats) — conflict-free A frags
#define PB 136          // W-tile smem row stride (136%32==8 -> conflict-free B frags)
#define MBLK ((NN + GM - 1) / GM)
#define GEMM_SMEM ((GM * PA + HD * PB) * 4)

// ---------------- scratch (device globals; no allocation allowed) ----------
__device__ float g_xt[(size_t)RR * NN * HD];   // 204.8 MB  xt[r][n][o]
__device__ float g_acc[(size_t)NN * HD];       // 25.6 MB   unnormalized aggregation
__device__ float g_denom[NN];                  // sum of exp per dst
__device__ float g_wq[RR * HD];                // W_r @ q
__device__ float g_wk[RR * HD];                // W_r @ k
__device__ float g_qi[NN * RR];                // x[n] . wq[r]
__device__ float g_kj[NN * RR];                // x[n] . wk[r]

__device__ __forceinline__ uint32_t f2tf32(float f) {
    uint32_t u;
    asm("cvt.rna.tf32.f32 %0, %1;" : "=r"(u) : "f"(f));
    return u;
}

// ---------------- zero acc + denom -----------------------------------------
__global__ void zero_kernel() {
    int i = blockIdx.x * blockDim.x + threadIdx.x;
    int stride = gridDim.x * blockDim.x;
    float4 z = make_float4(0.f, 0.f, 0.f, 0.f);
    float4* a4 = (float4*)g_acc;
    const int na4 = NN * HD / 4;
    for (int j = i; j < na4; j += stride) a4[j] = z;
    for (int j = i; j < NN; j += stride) g_denom[j] = 0.f;
}

// ---------------- Wq[r] = W_r @ q, Wk[r] = W_r @ k --------------------------
__global__ void wqwk_kernel(const float* __restrict__ W,
                            const float* __restrict__ q,
                            const float* __restrict__ k) {
    int w = (blockIdx.x * blockDim.x + threadIdx.x) >> 5;  // 0..1023 = r*128+d
    int lane = threadIdx.x & 31;
    if (w >= RR * HD) return;
    const float* row = W + (size_t)w * HD;
    float sq = 0.f, sk = 0.f;
#pragma unroll
    for (int j = lane; j < HD; j += 32) {
        float wv = row[j];
        sq += wv * q[j];
        sk += wv * k[j];
    }
#pragma unroll
    for (int o = 16; o; o >>= 1) {
        sq += __shfl_xor_sync(0xffffffffu, sq, o);
        sk += __shfl_xor_sync(0xffffffffu, sk, o);
    }
    if (lane == 0) {
        g_wq[w] = sq;
        g_wk[w] = sk;
    }
}

// ---------------- per-node logit tables: qi[n][r], kj[n][r] -----------------
__global__ void table_kernel(const float* __restrict__ x) {
    int n = (blockIdx.x * blockDim.x + threadIdx.x) >> 5;
    if (n >= NN) return;
    int lane = threadIdx.x & 31;
    float4 xv = ((const float4*)x)[(size_t)n * 32 + lane];
#pragma unroll
    for (int r = 0; r < RR; r++) {
        float4 wq = ((const float4*)g_wq)[r * 32 + lane];
        float4 wk = ((const float4*)g_wk)[r * 32 + lane];
        float sq = xv.x * wq.x + xv.y * wq.y + xv.z * wq.z + xv.w * wq.w;
        float sk = xv.x * wk.x + xv.y * wk.y + xv.z * wk.z + xv.w * wk.w;
#pragma unroll
        for (int o = 16; o; o >>= 1) {
            sq += __shfl_xor_sync(0xffffffffu, sq, o);
            sk += __shfl_xor_sync(0xffffffffu, sk, o);
        }
        if (lane == 0) {
            g_qi[n * RR + r] = sq;
            g_kj[n * RR + r] = sk;
        }
    }
}

// ---------------- xt[r] = x @ W_r  (tf32 mma.sync, 8 relations per block) ---
__global__ __launch_bounds__(256)
void xt_gemm(const float* __restrict__ x, const float* __restrict__ W) {
    extern __shared__ uint32_t sm[];
    uint32_t* As = sm;            // [GM][PA]  x tile (tf32 bits)
    uint32_t* Bs = sm + GM * PA;  // [HD][PB]  W_r tile (tf32 bits)
    int tid = threadIdx.x;
    int m0 = blockIdx.x * GM;

    // load x tile once, convert to tf32
    for (int idx = tid; idx < GM * 32; idx += 256) {
        int row = idx >> 5, c4 = idx & 31;
        int gm = m0 + row;
        float4 v = make_float4(0.f, 0.f, 0.f, 0.f);
        if (gm < NN) v = ((const float4*)x)[(size_t)gm * 32 + c4];
        uint4 u = make_uint4(f2tf32(v.x), f2tf32(v.y), f2tf32(v.z), f2tf32(v.w));
        *(uint4*)&As[row * PA + c4 * 4] = u;
    }

    int wid = tid >> 5, lane = tid & 31;
    int warpM = wid >> 1;        // 0..3 -> 32-row slab
    int warpN = wid & 1;         // 0..1 -> 64-col slab
    int g = lane >> 2, t = lane & 3;

    for (int r = 0; r < RR; r++) {
        // load W_r tile, convert to tf32
        for (int idx = tid; idx < HD * 32; idx += 256) {
            int row = idx >> 5, c4 = idx & 31;
            float4 v = ((const float4*)W)[(size_t)(r * HD + row) * 32 + c4];
            uint4 u = make_uint4(f2tf32(v.x), f2tf32(v.y), f2tf32(v.z), f2tf32(v.w));
            *(uint4*)&Bs[row * PB + c4 * 4] = u;
        }
        __syncthreads();

        float acc[2][8][4];
#pragma unroll
        for (int mt = 0; mt < 2; mt++)
#pragma unroll
            for (int nt = 0; nt < 8; nt++)
#pragma unroll
                for (int c = 0; c < 4; c++) acc[mt][nt][c] = 0.f;

        for (int k0 = 0; k0 < HD; k0 += 8) {
            uint32_t a[2][4];
#pragma unroll
            for (int mt = 0; mt < 2; mt++) {
                int rb = warpM * 32 + mt * 16 + g;
                a[mt][0] = As[rb * PA + k0 + t];
                a[mt][1] = As[(rb + 8) * PA + k0 + t];
                a[mt][2] = As[rb * PA + k0 + t + 4];
                a[mt][3] = As[(rb + 8) * PA + k0 + t + 4];
            }
            uint32_t b[8][2];
#pragma unroll
            for (int nt = 0; nt < 8; nt++) {
                int col = warpN * 64 + nt * 8 + g;
                b[nt][0] = Bs[(k0 + t) * PB + col];
                b[nt][1] = Bs[(k0 + t + 4) * PB + col];
            }
#pragma unroll
            for (int mt = 0; mt < 2; mt++)
#pragma unroll
                for (int nt = 0; nt < 8; nt++) {
                    asm volatile(
                        "mma.sync.aligned.m16n8k8.row.col.f32.tf32.tf32.f32 "
                        "{%0,%1,%2,%3}, {%4,%5,%6,%7}, {%8,%9}, {%0,%1,%2,%3};"
                        : "+f"(acc[mt][nt][0]), "+f"(acc[mt][nt][1]),
                          "+f"(acc[mt][nt][2]), "+f"(acc[mt][nt][3])
                        : "r"(a[mt][0]), "r"(a[mt][1]), "r"(a[mt][2]), "r"(a[mt][3]),
                          "r"(b[nt][0]), "r"(b[nt][1]));
                }
        }

        // store to xt[r]
#pragma unroll
        for (int mt = 0; mt < 2; mt++) {
            int row0 = m0 + warpM * 32 + mt * 16 + g;
#pragma unroll
            for (int nt = 0; nt < 8; nt++) {
                int col = warpN * 64 + nt * 8 + t * 2;
                if (row0 < NN) {
                    float2 v = make_float2(acc[mt][nt][0], acc[mt][nt][1]);
                    *(float2*)&g_xt[((size_t)r * NN + row0) * HD + col] = v;
                }
                if (row0 + 8 < NN) {
                    float2 v = make_float2(acc[mt][nt][2], acc[mt][nt][3]);
                    *(float2*)&g_xt[((size_t)r * NN + row0 + 8) * HD + col] = v;
                }
            }
        }
        __syncthreads();
    }
}

// ---------------- single edge pass: denom += ex; acc[dst] += ex*xt[r,src] ---
__global__ void edge_kernel(const int* __restrict__ ei,
                            const int* __restrict__ et) {
    int e = (blockIdx.x * blockDim.x + threadIdx.x) >> 5;
    if (e >= EE) return;
    int lane = threadIdx.x & 31;
    int src = __ldg(ei + e);
    int dst = __ldg(ei + EE + e);
    int r = __ldg(et + e);
    float al = g_qi[dst * RR + r] + g_kj[src * RR + r];
    al = al > 0.f ? al : 0.2f * al;           // leaky_relu
    float ex = __expf(al);                    // alpha ~ O(1): no max-shift
    if (lane == 0) atomicAdd(&g_denom[dst], ex);
    float4 v = ((const float4*)g_xt)[((size_t)r * NN + src) * 32 + lane];
    v.x *= ex; v.y *= ex; v.z *= ex; v.w *= ex;
    float* p = &g_acc[(size_t)dst * HD + lane * 4];
    asm volatile("red.global.add.v4.f32 [%0], {%1,%2,%3,%4};"
                 :: "l"(p), "f"(v.x), "f"(v.y), "f"(v.z), "f"(v.w)
                 : "memory");
}

// ---------------- out = relu(acc/denom + b) ---------------------------------
__global__ void epilogue_kernel(const float* __restrict__ bias,
                                float* __restrict__ out) {
    int i = blockIdx.x * blockDim.x + threadIdx.x;   // over NN*32 float4s
    if (i >= NN * 32) return;
    int n = i >> 5, c4 = i & 31;
    float inv = 1.0f / (g_denom[n] + 1e-16f);
    float4 v = ((const float4*)g_acc)[i];
    float4 bb = ((const float4*)bias)[c4];
    v.x = fmaxf(v.x * inv + bb.x, 0.f);
    v.y = fmaxf(v.y * inv + bb.y, 0.f);
    v.z = fmaxf(v.z * inv + bb.z, 0.f);
    v.w = fmaxf(v.w * inv + bb.w, 0.f);
    ((float4*)out)[i] = v;
}

// ---------------- driver ----------------------------------------------------
static void run_one_graph(const float* x, const int* ei, const int* et,
                          const float* W, const float* q, const float* k,
                          const float* b, float* out) {
    zero_kernel<<<1024, 256>>>();
    wqwk_kernel<<<(RR * HD) / 8, 256>>>(W, q, k);
    table_kernel<<<(NN + 7) / 8, 256>>>(x);
    xt_gemm<<<MBLK, 256, GEMM_SMEM>>>(x, W);
    edge_kernel<<<EE / 8, 256>>>(ei, et);
    epilogue_kernel<<<(NN * 32 + 255) / 256, 256>>>(b, out);
}

extern "C" void kernel_launch(void* const* d_in, const int* in_sizes, int n_in,
                              void* d_out, int out_size) {
    const float* x1  = (const float*)d_in[0];
    const int*   ei1 = (const int*)d_in[1];
    const int*   et1 = (const int*)d_in[2];
    const float* x2  = (const float*)d_in[3];
    const int*   ei2 = (const int*)d_in[4];
    const int*   et2 = (const int*)d_in[5];
    const float* W1  = (const float*)d_in[6];
    const float* q1  = (const float*)d_in[7];
    const float* k1  = (const float*)d_in[8];
    const float* b1  = (const float*)d_in[9];
    const float* W2  = (const float*)d_in[10];
    const float* q2  = (const float*)d_in[11];
    const float* k2  = (const float*)d_in[12];
    const float* b2  = (const float*)d_in[13];

    cudaFuncSetAttribute(xt_gemm, cudaFuncAttributeMaxDynamicSharedMemorySize,
                         GEMM_SMEM);

    float* out = (float*)d_out;
    run_one_graph(x1, ei1, et1, W1, q1, k1, b1, out);
    run_one_graph(x2, ei2, et2, W2, q2, k2, b2, out + (size_t)NN * HD);
}